// round 10
// baseline (speedup 1.0000x reference)
#include <cuda_runtime.h>
#include <cuda_fp16.h>
#include <cstdint>

#define N_TOKENS   8192
#define N_EXPERTS  256
#define D_MODEL    4096
#define N_GROUP    4
#define GROUP_SIZE 64
#define ROUTED_SCALING 2.5f
#define EPS_ROUTE  1e-10f
#define TIE_DELTA  1.2e-3f

// GEMM tiling: block 32x256, BK=32, 256 threads (8 warps, warp tile 32x32)
#define BM 32
#define BN 256
#define BK 32
#define CHUNKS (D_MODEL / BK)        // 128

// SMEM geometry (fp16 elems): 32 cols + 8 pad = 40 (80 B rows)
#define RS          40
#define A_ELEMS     (32 * RS)              // 1280
#define B_ELEMS     (256 * RS)             // 10240
#define A_BYTES     (A_ELEMS * 2)          // 2560
#define B_BYTES     (B_ELEMS * 2)          // 20480
#define A_STAGES    2
#define B_STAGES    4
#define OFF_B       (A_STAGES * A_BYTES)   // 5120
#define GEMM_SMEM   (A_STAGES * A_BYTES + B_STAGES * B_BYTES)  // 87040

// Epilogue smem views (reuse tile memory; all < GEMM_SMEM)
#define SC_PAD   257
#define OFF_SC   0                        // 32*257 floats = 32896 B
#define OFF_SGV  32896                    // 32*16 floats  = 2048 B
#define OFF_SGI  (32896 + 2048)           // 32*16 ints    = 2048 B
#define OFF_CNT  (32896 + 4096)           // 1 int
#define OFF_LIST (32896 + 4096 + 16)      // 32 ints

// ---------------------------------------------------------------------------
// Scratch: fp16 copy of gate_w
// ---------------------------------------------------------------------------
__device__ __half g_Bh[(size_t)N_EXPERTS * D_MODEL];

// ---------------------------------------------------------------------------
// helpers
// ---------------------------------------------------------------------------
__device__ __forceinline__ uint32_t smem_u32(const void* p) {
    uint32_t a;
    asm("{ .reg .u64 t; cvta.to.shared.u64 t, %1; cvt.u32.u64 %0, t; }"
        : "=r"(a) : "l"(p));
    return a;
}

__device__ __forceinline__ void ldsm4(uint32_t& r0, uint32_t& r1,
                                      uint32_t& r2, uint32_t& r3, uint32_t addr) {
    asm volatile("ldmatrix.sync.aligned.m8n8.x4.shared.b16 {%0,%1,%2,%3}, [%4];"
                 : "=r"(r0), "=r"(r1), "=r"(r2), "=r"(r3) : "r"(addr));
}

__device__ __forceinline__ void mma16816(float* c, const uint32_t* a,
                                         uint32_t b0, uint32_t b1) {
    asm volatile(
        "mma.sync.aligned.m16n8k16.row.col.f32.f16.f16.f32 "
        "{%0,%1,%2,%3}, {%4,%5,%6,%7}, {%8,%9}, {%0,%1,%2,%3};"
        : "+f"(c[0]), "+f"(c[1]), "+f"(c[2]), "+f"(c[3])
        : "r"(a[0]), "r"(a[1]), "r"(a[2]), "r"(a[3]), "r"(b0), "r"(b1));
}

__device__ __forceinline__ uint32_t pack_h2(float a, float b) {
    __half2 h = __floats2half2_rn(a, b);
    return *(uint32_t*)&h;
}

#define CP16(dst, src) \
    asm volatile("cp.async.cg.shared.global [%0], [%1], 16;" :: "r"(dst), "l"(src) : "memory")
#define CP_COMMIT() asm volatile("cp.async.commit_group;" ::: "memory")
#define CP_WAIT(n)  asm volatile("cp.async.wait_group %0;" :: "n"(n) : "memory")

// ---------------------------------------------------------------------------
// B convert: fp32 -> fp16
// ---------------------------------------------------------------------------
__global__ __launch_bounds__(256) void convert_b(const float* __restrict__ src) {
    int i = blockIdx.x * blockDim.x + threadIdx.x;
    const int n4 = N_EXPERTS * D_MODEL / 4;
    const int stride = gridDim.x * blockDim.x;
    const float4* s4 = (const float4*)src;
    uint2* h2 = (uint2*)g_Bh;
    for (; i < n4; i += stride) {
        float4 v = s4[i];
        h2[i] = make_uint2(pack_h2(v.x, v.y), pack_h2(v.z, v.w));
    }
}

// ---------------------------------------------------------------------------
// Fused fp16 GEMM + MoE gate epilogue. 256 threads, 2 CTAs/SM,
// 4-stage B ring with lookahead-2, 2-ahead A register prefetch.
// ---------------------------------------------------------------------------
__global__ __launch_bounds__(256, 2) void gemm_gate_fused(
    const float* __restrict__ A,     // [8192, 4096] hidden
    const float* __restrict__ Bw,    // [256, 4096] gate_w fp32 (exact redo)
    float* __restrict__ C,           // [8192, 256] logits out
    float* __restrict__ out_idx,     // [8192, 8]
    float* __restrict__ out_w)       // [8192, 8]
{
    extern __shared__ __align__(128) char smem_raw[];
    __half* smem = (__half*)smem_raw;
    const uint32_t sb = smem_u32(smem_raw);

    const int tid = threadIdx.x;
    const int lid = tid & 31;
    const int wid = tid >> 5;            // 0..7 -> n slice [wid*32, +32)
    const int bm = blockIdx.x * BM;

    // A global-load mapping: 8 threads/row, 4 floats each (32x32 fp32 tile)
    const int ar = tid >> 3;             // 0..31
    const int ac = (tid & 7) * 4;        // col segment

    float4 buf;                          // A prefetch register buffer
    float acc[2][4][4];
    #pragma unroll
    for (int i = 0; i < 2; i++)
        #pragma unroll
        for (int j = 0; j < 4; j++)
            #pragma unroll
            for (int k = 0; k < 4; k++) acc[i][j][k] = 0.0f;

    // ldmatrix coords
    const int a_row = lid & 15;
    const int a_col = (lid >> 4) * 8;
    const int b_row = wid * 32 + ((lid >> 4) << 3) + (lid & 7);
    const int b_col = ((lid >> 3) & 1) * 8;

    const __half* gB = g_Bh;

    auto issue_b = [&](int c, int s) {
        const int k0 = c * BK;
        const uint32_t b_s = sb + OFF_B + s * B_BYTES;
        #pragma unroll
        for (int i = 0; i < 4; i++) {
            int id = i * 256 + tid;       // 0..1023
            int row = id >> 2, sg = id & 3;
            uint32_t doff = (uint32_t)(row * RS + sg * 8) * 2;
            CP16(b_s + doff, gB + (size_t)row * D_MODEL + k0 + sg * 8);
        }
        CP_COMMIT();
    };

    auto load_a = [&](int c) {
        const int k0 = c * BK;
        buf = *(const float4*)(A + (size_t)(bm + ar) * D_MODEL + k0 + ac);
    };

    auto store_a = [&](int s) {
        __half* sh = smem + s * A_ELEMS;   // A at offset 0
        uint32_t h0 = pack_h2(buf.x, buf.y);
        uint32_t h1 = pack_h2(buf.z, buf.w);
        *(uint2*)(sh + ar * RS + ac) = make_uint2(h0, h1);
    };

    auto compute = [&](int sB, int sA) {
        const uint32_t a_b = sb + sA * A_BYTES;
        const uint32_t b_b = sb + OFF_B + sB * B_BYTES;
        #pragma unroll
        for (int ks = 0; ks < 2; ks++) {
            uint32_t bh[2][4];
            #pragma unroll
            for (int half = 0; half < 2; half++) {
                uint32_t off = (uint32_t)((b_row + half * 16) * RS + b_col + ks * 16) * 2;
                ldsm4(bh[half][0], bh[half][1], bh[half][2], bh[half][3], b_b + off);
            }
            #pragma unroll
            for (int mt = 0; mt < 2; mt++) {
                uint32_t off = (uint32_t)((a_row + mt * 16) * RS + a_col + ks * 16) * 2;
                uint32_t ah[4];
                ldsm4(ah[0], ah[1], ah[2], ah[3], a_b + off);
                #pragma unroll
                for (int nt = 0; nt < 4; nt++) {
                    uint32_t b0 = bh[nt >> 1][(nt & 1) * 2];
                    uint32_t b1 = bh[nt >> 1][(nt & 1) * 2 + 1];
                    mma16816(acc[mt][nt], ah, b0, b1);
                }
            }
        }
    };

    // prologue: B chunks 0,1 in flight; A chunk 0 in smem; A chunk 1 in regs
    issue_b(0, 0);
    issue_b(1, 1);
    load_a(0);
    store_a(0);
    load_a(1);

    #pragma unroll 1
    for (int c = 0; c < CHUNKS; c++) {
        if (c + 2 < CHUNKS) {
            issue_b(c + 2, (c + 2) & 3);
            CP_WAIT(2);                    // chunk c's B complete
        } else {
            CP_WAIT(0);                    // tail: drain everything
        }
        __syncthreads();
        if (c + 1 < CHUNKS) store_a((c + 1) & 1);   // from buf (chunk c+1)
        if (c + 2 < CHUNKS) load_a(c + 2);          // prefetch into buf
        compute(c & 3, c & 1);
    }

    // ------------------ fused epilogue ------------------
    float* sc    = (float*)(smem_raw + OFF_SC);
    float* sgv   = (float*)(smem_raw + OFF_SGV);
    int*   sgi   = (int*)(smem_raw + OFF_SGI);
    int*   s_cnt = (int*)(smem_raw + OFF_CNT);
    int*   s_lst = (int*)(smem_raw + OFF_LIST);

    __syncthreads();    // all warps done computing before smem reuse
    if (tid == 0) *s_cnt = 0;

    // acc -> smem logits + global logits
    #pragma unroll
    for (int mt = 0; mt < 2; mt++) {
        const int r0 = mt * 16 + (lid >> 2);
        #pragma unroll
        for (int nt = 0; nt < 4; nt++) {
            const int col = wid * 32 + nt * 8 + (lid & 3) * 2;
            sc[r0 * SC_PAD + col]           = acc[mt][nt][0];
            sc[r0 * SC_PAD + col + 1]       = acc[mt][nt][1];
            sc[(r0 + 8) * SC_PAD + col]     = acc[mt][nt][2];
            sc[(r0 + 8) * SC_PAD + col + 1] = acc[mt][nt][3];
            *(float2*)&C[(size_t)(bm + r0) * N_EXPERTS + col] =
                make_float2(acc[mt][nt][0], acc[mt][nt][1]);
            *(float2*)&C[(size_t)(bm + r0 + 8) * N_EXPERTS + col] =
                make_float2(acc[mt][nt][2], acc[mt][nt][3]);
        }
    }
    __syncthreads();

    // per-(token, group) top-4 scan
    if (tid < 128) {
        const int token = tid >> 2;
        const int g = tid & 3;
        const int base = g * GROUP_SIZE;
        const int ro = token * SC_PAD;
        float v0 = -1e30f, v1 = -1e30f, v2 = -1e30f, v3 = -1e30f;
        int i0 = 0, i1 = 0, i2 = 0, i3 = 0;
        #pragma unroll 8
        for (int j = 0; j < GROUP_SIZE; j++) {
            int jj = (j + 8 * g) & 63;
            float x = sc[ro + base + jj];
            int ix = base + jj;
            if (x > v0)      { v3=v2;i3=i2; v2=v1;i2=i1; v1=v0;i1=i0; v0=x;i0=ix; }
            else if (x > v1) { v3=v2;i3=i2; v2=v1;i2=i1; v1=x;i1=ix; }
            else if (x > v2) { v3=v2;i3=i2; v2=x;i2=ix; }
            else if (x > v3) { v3=x;i3=ix; }
        }
        const int o = token * 16 + g * 4;
        sgv[o] = v0; sgv[o+1] = v1; sgv[o+2] = v2; sgv[o+3] = v3;
        sgi[o] = i0; sgi[o+1] = i1; sgi[o+2] = i2; sgi[o+3] = i3;
    }
    __syncthreads();

    // flag near-tie tokens
    if (tid < 32) {
        bool f = false;
        #pragma unroll
        for (int g = 0; g < N_GROUP; g++) {
            const int o = tid * 16 + g * 4;
            float v0 = sgv[o], v1 = sgv[o+1], v2 = sgv[o+2];
            f |= ((v0 - v1) < TIE_DELTA) || ((v1 - v2) < TIE_DELTA);
        }
        if (f) { int p = atomicAdd(s_cnt, 1); s_lst[p] = tid; }
    }
    __syncthreads();

    const int cnt = *s_cnt;
    for (int it = 0; it < cnt; it++) {
        const int token = s_lst[it];
        {
            const int cand = tid >> 4;      // 0..15
            const int ln = tid & 15;
            const int e = sgi[token * 16 + cand];
            const float* hrow = A + (size_t)(bm + token) * D_MODEL;
            const float* wrow = Bw + (size_t)e * D_MODEL;
            float p = 0.0f;
            #pragma unroll 8
            for (int k = 0; k < D_MODEL / 16; k++)
                p = fmaf(hrow[ln + 16 * k], wrow[ln + 16 * k], p);
            #pragma unroll
            for (int off = 8; off; off >>= 1)
                p += __shfl_down_sync(0xffffffffu, p, off, 16);
            if (ln == 0) sgv[token * 16 + cand] = p;
        }
        __syncthreads();
        if (tid < 4) {
            const int o = token * 16 + tid * 4;
            #pragma unroll
            for (int a = 0; a < 3; a++) {
                int best = a;
                #pragma unroll
                for (int b = 1; b < 4; b++) {
                    if (b <= a) continue;
                    if (sgv[o+b] > sgv[o+best] ||
                        (sgv[o+b] == sgv[o+best] && sgi[o+b] < sgi[o+best]))
                        best = b;
                }
                float tv = sgv[o+a]; sgv[o+a] = sgv[o+best]; sgv[o+best] = tv;
                int ti = sgi[o+a]; sgi[o+a] = sgi[o+best]; sgi[o+best] = ti;
            }
        }
        __syncthreads();
    }

    // final outputs
    if (tid < 32) {
        float w8[8]; int i8[8];
        float sum = 0.0f;
        #pragma unroll
        for (int g = 0; g < N_GROUP; g++) {
            #pragma unroll
            for (int k = 0; k < 2; k++) {
                const int o = tid * 16 + g * 4 + k;
                float s = 1.0f / (1.0f + __expf(-sgv[o]));
                w8[g * 2 + k] = s;
                i8[g * 2 + k] = sgi[o];
                sum += s;
            }
        }
        float scale = ROUTED_SCALING / (sum + EPS_ROUTE);
        #pragma unroll
        for (int j = 0; j < 8; j++) {
            out_idx[(size_t)(bm + tid) * 8 + j] = (float)i8[j];
            out_w[(size_t)(bm + tid) * 8 + j]   = w8[j] * scale;
        }
    }
}

// ---------------------------------------------------------------------------
// Launch
// ---------------------------------------------------------------------------
extern "C" void kernel_launch(void* const* d_in, const int* in_sizes, int n_in,
                              void* d_out, int out_size) {
    const float* hidden = (const float*)d_in[0];   // [8192, 4096]
    const float* gate_w = (const float*)d_in[1];   // [256, 4096]

    float* out = (float*)d_out;
    float* out_idx    = out;
    float* out_w      = out + (size_t)N_TOKENS * 8;
    float* out_logits = out + (size_t)N_TOKENS * 16;

    convert_b<<<256, 256>>>(gate_w);

    cudaFuncSetAttribute(gemm_gate_fused,
                         cudaFuncAttributeMaxDynamicSharedMemorySize, GEMM_SMEM);
    gemm_gate_fused<<<N_TOKENS / BM, 256, GEMM_SMEM>>>(
        hidden, gate_w, out_logits, out_idx, out_w);
}

// round 11
// speedup vs baseline: 1.0429x; 1.0429x over previous
#include <cuda_runtime.h>
#include <cuda_fp16.h>
#include <cstdint>

#define N_TOKENS   8192
#define N_EXPERTS  256
#define D_MODEL    4096
#define N_GROUP    4
#define GROUP_SIZE 64
#define ROUTED_SCALING 2.5f
#define EPS_ROUTE  1e-10f
#define TIE_DELTA  1.2e-3f

// GEMM tiling: block 32x256, BK=64, 256 threads
// 8 warps: warp_n = wid&3 (64-col slice), warp_k = wid>>2 (2 of 4 ks-steps)
#define BM 32
#define BN 256
#define BK 64
#define CHUNKS (D_MODEL / BK)        // 64

// SMEM geometry (fp16 elems): 64 cols + 8 pad = 72 (144 B rows)
#define RS          72
#define A_ELEMS     (32 * RS)              // 2304
#define B_ELEMS     (256 * RS)             // 18432
#define A_BYTES     (A_ELEMS * 2)          // 4608
#define B_BYTES     (B_ELEMS * 2)          // 36864
#define STAGE_BYTES (A_BYTES + B_BYTES)    // 41472
#define OFF_BT      A_BYTES                // B after A within stage
#define GEMM_SMEM   (2 * STAGE_BYTES)      // 82944

// Epilogue smem views (reuse tile memory; all < GEMM_SMEM)
#define SC_PAD   257
#define OFF_SC   0                        // 32*257 floats = 32896 B
#define OFF_SGV  32896                    // 32*16 floats  = 2048 B
#define OFF_SGI  (32896 + 2048)           // 32*16 ints    = 2048 B
#define OFF_CNT  (32896 + 4096)           // 1 int
#define OFF_LIST (32896 + 4096 + 16)      // 32 ints

// ---------------------------------------------------------------------------
// Scratch: fp16 copy of gate_w
// ---------------------------------------------------------------------------
__device__ __half g_Bh[(size_t)N_EXPERTS * D_MODEL];

// ---------------------------------------------------------------------------
// helpers
// ---------------------------------------------------------------------------
__device__ __forceinline__ uint32_t smem_u32(const void* p) {
    uint32_t a;
    asm("{ .reg .u64 t; cvta.to.shared.u64 t, %1; cvt.u32.u64 %0, t; }"
        : "=r"(a) : "l"(p));
    return a;
}

__device__ __forceinline__ void ldsm4(uint32_t& r0, uint32_t& r1,
                                      uint32_t& r2, uint32_t& r3, uint32_t addr) {
    asm volatile("ldmatrix.sync.aligned.m8n8.x4.shared.b16 {%0,%1,%2,%3}, [%4];"
                 : "=r"(r0), "=r"(r1), "=r"(r2), "=r"(r3) : "r"(addr));
}

__device__ __forceinline__ void mma16816(float* c, const uint32_t* a,
                                         uint32_t b0, uint32_t b1) {
    asm volatile(
        "mma.sync.aligned.m16n8k16.row.col.f32.f16.f16.f32 "
        "{%0,%1,%2,%3}, {%4,%5,%6,%7}, {%8,%9}, {%0,%1,%2,%3};"
        : "+f"(c[0]), "+f"(c[1]), "+f"(c[2]), "+f"(c[3])
        : "r"(a[0]), "r"(a[1]), "r"(a[2]), "r"(a[3]), "r"(b0), "r"(b1));
}

__device__ __forceinline__ uint32_t pack_h2(float a, float b) {
    __half2 h = __floats2half2_rn(a, b);
    return *(uint32_t*)&h;
}

#define CP16(dst, src) \
    asm volatile("cp.async.cg.shared.global [%0], [%1], 16;" :: "r"(dst), "l"(src) : "memory")
#define CP_COMMIT() asm volatile("cp.async.commit_group;" ::: "memory")
#define CP_WAIT(n)  asm volatile("cp.async.wait_group %0;" :: "n"(n) : "memory")

// ---------------------------------------------------------------------------
// B convert: fp32 -> fp16
// ---------------------------------------------------------------------------
__global__ __launch_bounds__(256) void convert_b(const float* __restrict__ src) {
    int i = blockIdx.x * blockDim.x + threadIdx.x;
    const int n4 = N_EXPERTS * D_MODEL / 4;
    const int stride = gridDim.x * blockDim.x;
    const float4* s4 = (const float4*)src;
    uint2* h2 = (uint2*)g_Bh;
    for (; i < n4; i += stride) {
        float4 v = s4[i];
        h2[i] = make_uint2(pack_h2(v.x, v.y), pack_h2(v.z, v.w));
    }
}

// ---------------------------------------------------------------------------
// Fused fp16 GEMM + MoE gate epilogue. 256 threads, 2 CTAs/SM.
// Warp tile 32x64 (16 indep acc chains), K-split across warp halves.
// ---------------------------------------------------------------------------
__global__ __launch_bounds__(256, 2) void gemm_gate_fused(
    const float* __restrict__ A,     // [8192, 4096] hidden
    const float* __restrict__ Bw,    // [256, 4096] gate_w fp32 (exact redo)
    float* __restrict__ C,           // [8192, 256] logits out
    float* __restrict__ out_idx,     // [8192, 8]
    float* __restrict__ out_w)       // [8192, 8]
{
    extern __shared__ __align__(128) char smem_raw[];
    __half* smem = (__half*)smem_raw;
    const uint32_t sb = smem_u32(smem_raw);

    const int tid = threadIdx.x;
    const int lid = tid & 31;
    const int wid = tid >> 5;            // 0..7
    const int warp_n = wid & 3;          // n slice [warp_n*64, +64)
    const int warp_k = wid >> 2;         // ks half: {warp_k*2, warp_k*2+1}
    const int bm = blockIdx.x * BM;

    // A global-load mapping: 8 threads/row, 8 floats each (32x64 fp32 tile)
    const int ar = tid >> 3;             // 0..31
    const int ac = (tid & 7) * 8;        // col segment

    float4 buf[2];
    float acc[2][8][4];
    #pragma unroll
    for (int i = 0; i < 2; i++)
        #pragma unroll
        for (int j = 0; j < 8; j++)
            #pragma unroll
            for (int k = 0; k < 4; k++) acc[i][j][k] = 0.0f;

    // ldmatrix coords
    const int a_row = lid & 15;
    const int a_col = (lid >> 4) * 8;
    const int b_row = warp_n * 64 + ((lid >> 4) << 3) + (lid & 7);
    const int b_col = ((lid >> 3) & 1) * 8;

    const __half* gB = g_Bh;

    auto issue_b = [&](int c, int s) {
        const int k0 = c * BK;
        const uint32_t b_s = sb + s * STAGE_BYTES + OFF_BT;
        #pragma unroll
        for (int i = 0; i < 8; i++) {
            int id = i * 256 + tid;       // 0..2047
            int row = id >> 3, sg = id & 7;
            uint32_t doff = (uint32_t)(row * RS + sg * 8) * 2;
            CP16(b_s + doff, gB + (size_t)row * D_MODEL + k0 + sg * 8);
        }
        CP_COMMIT();
    };

    auto load_a = [&](int c) {
        const int k0 = c * BK;
        const float* base = A + (size_t)(bm + ar) * D_MODEL + k0 + ac;
        buf[0] = *(const float4*)(base);
        buf[1] = *(const float4*)(base + 4);
    };

    auto store_a = [&](int s) {
        __half* sh = smem + s * (STAGE_BYTES / 2);   // A at stage start
        uint32_t hw[4];
        hw[0] = pack_h2(buf[0].x, buf[0].y);
        hw[1] = pack_h2(buf[0].z, buf[0].w);
        hw[2] = pack_h2(buf[1].x, buf[1].y);
        hw[3] = pack_h2(buf[1].z, buf[1].w);
        *(uint4*)(sh + ar * RS + ac) = make_uint4(hw[0], hw[1], hw[2], hw[3]);
    };

    auto compute = [&](int s) {
        const uint32_t a_b = sb + s * STAGE_BYTES;
        const uint32_t b_b = a_b + OFF_BT;
        #pragma unroll
        for (int kk = 0; kk < 2; kk++) {
            const int ks = warp_k * 2 + kk;
            uint32_t bh[4][4];
            #pragma unroll
            for (int half = 0; half < 4; half++) {
                uint32_t off = (uint32_t)((b_row + half * 16) * RS + b_col + ks * 16) * 2;
                ldsm4(bh[half][0], bh[half][1], bh[half][2], bh[half][3], b_b + off);
            }
            #pragma unroll
            for (int mt = 0; mt < 2; mt++) {
                uint32_t off = (uint32_t)((a_row + mt * 16) * RS + a_col + ks * 16) * 2;
                uint32_t ah[4];
                ldsm4(ah[0], ah[1], ah[2], ah[3], a_b + off);
                #pragma unroll
                for (int nt = 0; nt < 8; nt++) {
                    uint32_t b0 = bh[nt >> 1][(nt & 1) * 2];
                    uint32_t b1 = bh[nt >> 1][(nt & 1) * 2 + 1];
                    mma16816(acc[mt][nt], ah, b0, b1);
                }
            }
        }
    };

    // prologue
    issue_b(0, 0);
    load_a(0);
    store_a(0);
    CP_WAIT(0);
    __syncthreads();

    #pragma unroll 1
    for (int c = 0; c < CHUNKS; c++) {
        const int s = c & 1;
        if (c + 1 < CHUNKS) { issue_b(c + 1, s ^ 1); load_a(c + 1); }
        compute(s);
        if (c + 1 < CHUNKS) store_a(s ^ 1);
        CP_WAIT(0);
        __syncthreads();
    }

    // ------------------ fused epilogue ------------------
    float* sc    = (float*)(smem_raw + OFF_SC);
    float* sgv   = (float*)(smem_raw + OFF_SGV);
    int*   sgi   = (int*)(smem_raw + OFF_SGI);
    int*   s_cnt = (int*)(smem_raw + OFF_CNT);
    int*   s_lst = (int*)(smem_raw + OFF_LIST);

    if (tid == 0) *s_cnt = 0;

    // K-split reduction: warps 0-3 store partials, warps 4-7 add theirs.
    if (wid < 4) {
        #pragma unroll
        for (int mt = 0; mt < 2; mt++) {
            const int r0 = mt * 16 + (lid >> 2);
            #pragma unroll
            for (int nt = 0; nt < 8; nt++) {
                const int col = warp_n * 64 + nt * 8 + (lid & 3) * 2;
                sc[r0 * SC_PAD + col]           = acc[mt][nt][0];
                sc[r0 * SC_PAD + col + 1]       = acc[mt][nt][1];
                sc[(r0 + 8) * SC_PAD + col]     = acc[mt][nt][2];
                sc[(r0 + 8) * SC_PAD + col + 1] = acc[mt][nt][3];
            }
        }
    }
    __syncthreads();
    if (wid >= 4) {
        #pragma unroll
        for (int mt = 0; mt < 2; mt++) {
            const int r0 = mt * 16 + (lid >> 2);
            #pragma unroll
            for (int nt = 0; nt < 8; nt++) {
                const int col = warp_n * 64 + nt * 8 + (lid & 3) * 2;
                sc[r0 * SC_PAD + col]           += acc[mt][nt][0];
                sc[r0 * SC_PAD + col + 1]       += acc[mt][nt][1];
                sc[(r0 + 8) * SC_PAD + col]     += acc[mt][nt][2];
                sc[(r0 + 8) * SC_PAD + col + 1] += acc[mt][nt][3];
            }
        }
    }
    __syncthreads();

    // coalesced logits writeback from smem
    #pragma unroll 4
    for (int r = 0; r < BM; r++)
        C[(size_t)(bm + r) * N_EXPERTS + tid] = sc[r * SC_PAD + tid];

    // per-(token, group) top-4 scan
    if (tid < 128) {
        const int token = tid >> 2;
        const int g = tid & 3;
        const int base = g * GROUP_SIZE;
        const int ro = token * SC_PAD;
        float v0 = -1e30f, v1 = -1e30f, v2 = -1e30f, v3 = -1e30f;
        int i0 = 0, i1 = 0, i2 = 0, i3 = 0;
        #pragma unroll 8
        for (int j = 0; j < GROUP_SIZE; j++) {
            int jj = (j + 8 * g) & 63;
            float x = sc[ro + base + jj];
            int ix = base + jj;
            if (x > v0)      { v3=v2;i3=i2; v2=v1;i2=i1; v1=v0;i1=i0; v0=x;i0=ix; }
            else if (x > v1) { v3=v2;i3=i2; v2=v1;i2=i1; v1=x;i1=ix; }
            else if (x > v2) { v3=v2;i3=i2; v2=x;i2=ix; }
            else if (x > v3) { v3=x;i3=ix; }
        }
        const int o = token * 16 + g * 4;
        sgv[o] = v0; sgv[o+1] = v1; sgv[o+2] = v2; sgv[o+3] = v3;
        sgi[o] = i0; sgi[o+1] = i1; sgi[o+2] = i2; sgi[o+3] = i3;
    }
    __syncthreads();

    // flag near-tie tokens
    if (tid < 32) {
        bool f = false;
        #pragma unroll
        for (int g = 0; g < N_GROUP; g++) {
            const int o = tid * 16 + g * 4;
            float v0 = sgv[o], v1 = sgv[o+1], v2 = sgv[o+2];
            f |= ((v0 - v1) < TIE_DELTA) || ((v1 - v2) < TIE_DELTA);
        }
        if (f) { int p = atomicAdd(s_cnt, 1); s_lst[p] = tid; }
    }
    __syncthreads();

    const int cnt = *s_cnt;
    for (int it = 0; it < cnt; it++) {
        const int token = s_lst[it];
        {
            const int cand = tid >> 4;      // 0..15
            const int ln = tid & 15;
            const int e = sgi[token * 16 + cand];
            const float* hrow = A + (size_t)(bm + token) * D_MODEL;
            const float* wrow = Bw + (size_t)e * D_MODEL;
            float p = 0.0f;
            #pragma unroll 8
            for (int k = 0; k < D_MODEL / 16; k++)
                p = fmaf(hrow[ln + 16 * k], wrow[ln + 16 * k], p);
            #pragma unroll
            for (int off = 8; off; off >>= 1)
                p += __shfl_down_sync(0xffffffffu, p, off, 16);
            if (ln == 0) sgv[token * 16 + cand] = p;
        }
        __syncthreads();
        if (tid < 4) {
            const int o = token * 16 + tid * 4;
            #pragma unroll
            for (int a = 0; a < 3; a++) {
                int best = a;
                #pragma unroll
                for (int b = 1; b < 4; b++) {
                    if (b <= a) continue;
                    if (sgv[o+b] > sgv[o+best] ||
                        (sgv[o+b] == sgv[o+best] && sgi[o+b] < sgi[o+best]))
                        best = b;
                }
                float tv = sgv[o+a]; sgv[o+a] = sgv[o+best]; sgv[o+best] = tv;
                int ti = sgi[o+a]; sgi[o+a] = sgi[o+best]; sgi[o+best] = ti;
            }
        }
        __syncthreads();
    }

    // final outputs
    if (tid < 32) {
        float w8[8]; int i8[8];
        float sum = 0.0f;
        #pragma unroll
        for (int g = 0; g < N_GROUP; g++) {
            #pragma unroll
            for (int k = 0; k < 2; k++) {
                const int o = tid * 16 + g * 4 + k;
                float s = 1.0f / (1.0f + __expf(-sgv[o]));
                w8[g * 2 + k] = s;
                i8[g * 2 + k] = sgi[o];
                sum += s;
            }
        }
        float scale = ROUTED_SCALING / (sum + EPS_ROUTE);
        #pragma unroll
        for (int j = 0; j < 8; j++) {
            out_idx[(size_t)(bm + tid) * 8 + j] = (float)i8[j];
            out_w[(size_t)(bm + tid) * 8 + j]   = w8[j] * scale;
        }
    }
}

// ---------------------------------------------------------------------------
// Launch
// ---------------------------------------------------------------------------
extern "C" void kernel_launch(void* const* d_in, const int* in_sizes, int n_in,
                              void* d_out, int out_size) {
    const float* hidden = (const float*)d_in[0];   // [8192, 4096]
    const float* gate_w = (const float*)d_in[1];   // [256, 4096]

    float* out = (float*)d_out;
    float* out_idx    = out;
    float* out_w      = out + (size_t)N_TOKENS * 8;
    float* out_logits = out + (size_t)N_TOKENS * 16;

    convert_b<<<256, 256>>>(gate_w);

    cudaFuncSetAttribute(gemm_gate_fused,
                         cudaFuncAttributeMaxDynamicSharedMemorySize, GEMM_SMEM);
    gemm_gate_fused<<<N_TOKENS / BM, 256, GEMM_SMEM>>>(
        hidden, gate_w, out_logits, out_idx, out_w);
}

// round 12
// speedup vs baseline: 1.2112x; 1.1614x over previous
#include <cuda_runtime.h>
#include <cuda_fp16.h>
#include <cstdint>

#define N_TOKENS   8192
#define N_EXPERTS  256
#define D_MODEL    4096
#define N_GROUP    4
#define GROUP_SIZE 64
#define ROUTED_SCALING 2.5f
#define EPS_ROUTE  1e-10f
#define TIE_DELTA  1.2e-3f

// GEMM tiling: block 32x256, BK=64, 256 threads (8 warps, warp tile 32x32)
#define BM 32
#define BN 256
#define BK 64
#define CHUNKS (D_MODEL / BK)        // 64

// SMEM geometry: exact 128-B rows (64 fp16), SW128 XOR swizzle, no padding.
#define ROWB        128                      // bytes per row
#define A_BYTES     (32 * ROWB)              // 4096
#define B_BYTES     (256 * ROWB)             // 32768
#define A_STAGES    2
#define B_STAGES    3
#define OFF_B       (A_STAGES * A_BYTES)     // 8192
#define GEMM_SMEM   (OFF_B + B_STAGES * B_BYTES)   // 106496 (104 KB)

// SW128 swizzle on byte offsets (XOR bits [4:6] with row bits [7:9])
#define SWZ(x) ((x) ^ (((x) >> 3) & 0x70))

// Epilogue smem views (reuse tile memory; all < GEMM_SMEM)
#define SC_PAD   257
#define OFF_SC   0                        // 32*257 floats = 32896 B
#define OFF_SGV  32896                    // 32*16 floats  = 2048 B
#define OFF_SGI  (32896 + 2048)           // 32*16 ints    = 2048 B
#define OFF_CNT  (32896 + 4096)           // 1 int
#define OFF_LIST (32896 + 4096 + 16)      // 32 ints

// ---------------------------------------------------------------------------
// Scratch: fp16 copy of gate_w
// ---------------------------------------------------------------------------
__device__ __half g_Bh[(size_t)N_EXPERTS * D_MODEL];

// ---------------------------------------------------------------------------
// helpers
// ---------------------------------------------------------------------------
__device__ __forceinline__ uint32_t smem_u32(const void* p) {
    uint32_t a;
    asm("{ .reg .u64 t; cvta.to.shared.u64 t, %1; cvt.u32.u64 %0, t; }"
        : "=r"(a) : "l"(p));
    return a;
}

__device__ __forceinline__ void ldsm4(uint32_t& r0, uint32_t& r1,
                                      uint32_t& r2, uint32_t& r3, uint32_t addr) {
    asm volatile("ldmatrix.sync.aligned.m8n8.x4.shared.b16 {%0,%1,%2,%3}, [%4];"
                 : "=r"(r0), "=r"(r1), "=r"(r2), "=r"(r3) : "r"(addr));
}

__device__ __forceinline__ void mma16816(float* c, const uint32_t* a,
                                         uint32_t b0, uint32_t b1) {
    asm volatile(
        "mma.sync.aligned.m16n8k16.row.col.f32.f16.f16.f32 "
        "{%0,%1,%2,%3}, {%4,%5,%6,%7}, {%8,%9}, {%0,%1,%2,%3};"
        : "+f"(c[0]), "+f"(c[1]), "+f"(c[2]), "+f"(c[3])
        : "r"(a[0]), "r"(a[1]), "r"(a[2]), "r"(a[3]), "r"(b0), "r"(b1));
}

__device__ __forceinline__ uint32_t pack_h2(float a, float b) {
    __half2 h = __floats2half2_rn(a, b);
    return *(uint32_t*)&h;
}

#define CP16(dst, src) \
    asm volatile("cp.async.cg.shared.global [%0], [%1], 16;" :: "r"(dst), "l"(src) : "memory")
#define CP_COMMIT() asm volatile("cp.async.commit_group;" ::: "memory")
#define CP_WAIT(n)  asm volatile("cp.async.wait_group %0;" :: "n"(n) : "memory")

// ---------------------------------------------------------------------------
// B convert: fp32 -> fp16
// ---------------------------------------------------------------------------
__global__ __launch_bounds__(256) void convert_b(const float* __restrict__ src) {
    int i = blockIdx.x * blockDim.x + threadIdx.x;
    const int n4 = N_EXPERTS * D_MODEL / 4;
    const int stride = gridDim.x * blockDim.x;
    const float4* s4 = (const float4*)src;
    uint2* h2 = (uint2*)g_Bh;
    for (; i < n4; i += stride) {
        float4 v = s4[i];
        h2[i] = make_uint2(pack_h2(v.x, v.y), pack_h2(v.z, v.w));
    }
}

// ---------------------------------------------------------------------------
// Fused fp16 GEMM + MoE gate epilogue. 256 threads, 2 CTAs/SM.
// 3-stage B ring, one-chunk B lookahead, one-chunk A register prefetch.
// ---------------------------------------------------------------------------
__global__ __launch_bounds__(256, 2) void gemm_gate_fused(
    const float* __restrict__ A,     // [8192, 4096] hidden
    const float* __restrict__ Bw,    // [256, 4096] gate_w fp32 (exact redo)
    float* __restrict__ C,           // [8192, 256] logits out
    float* __restrict__ out_idx,     // [8192, 8]
    float* __restrict__ out_w)       // [8192, 8]
{
    extern __shared__ __align__(128) char smem_raw[];
    const uint32_t sb = smem_u32(smem_raw);

    const int tid = threadIdx.x;
    const int lid = tid & 31;
    const int wid = tid >> 5;            // 0..7 -> n slice [wid*32, +32)
    const int bm = blockIdx.x * BM;

    // A global-load mapping: 8 threads/row, 8 floats each (32x64 fp32 tile)
    const int ar = tid >> 3;             // 0..31
    const int ac = (tid & 7) * 8;        // col (elements)

    float4 buf[2];                       // A prefetch registers
    float acc[2][4][4];
    #pragma unroll
    for (int i = 0; i < 2; i++)
        #pragma unroll
        for (int j = 0; j < 4; j++)
            #pragma unroll
            for (int k = 0; k < 4; k++) acc[i][j][k] = 0.0f;

    // ldmatrix coords (rows; cols in elements)
    const int a_row = lid & 15;
    const int a_col = (lid >> 4) * 8;
    const int b_row = wid * 32 + ((lid >> 4) << 3) + (lid & 7);
    const int b_col = ((lid >> 3) & 1) * 8;

    const __half* gB = g_Bh;

    auto issue_b = [&](int c, int s) {
        const int k0 = c * BK;
        const uint32_t b_s = sb + OFF_B + s * B_BYTES;
        #pragma unroll
        for (int i = 0; i < 8; i++) {
            int id = i * 256 + tid;       // 0..2047
            int row = id >> 3, sg = id & 7;
            uint32_t doff = SWZ((uint32_t)(row * ROWB + sg * 16));
            CP16(b_s + doff, gB + (size_t)row * D_MODEL + k0 + sg * 8);
        }
        CP_COMMIT();
    };

    auto load_a = [&](int c) {
        const int k0 = c * BK;
        const float* base = A + (size_t)(bm + ar) * D_MODEL + k0 + ac;
        buf[0] = *(const float4*)(base);
        buf[1] = *(const float4*)(base + 4);
    };

    auto store_a = [&](int s) {
        const uint32_t a_s = sb + s * A_BYTES;
        uint32_t hw[4];
        hw[0] = pack_h2(buf[0].x, buf[0].y);
        hw[1] = pack_h2(buf[0].z, buf[0].w);
        hw[2] = pack_h2(buf[1].x, buf[1].y);
        hw[3] = pack_h2(buf[1].z, buf[1].w);
        uint32_t doff = SWZ((uint32_t)(ar * ROWB + ac * 2));
        *(uint4*)(smem_raw + (a_s - sb) + doff) = make_uint4(hw[0], hw[1], hw[2], hw[3]);
    };

    auto compute = [&](int s) {
        const uint32_t a_b = sb + (s & 1) * A_BYTES;
        const uint32_t b_b = sb + OFF_B + (s % B_STAGES) * B_BYTES;
        #pragma unroll
        for (int ks = 0; ks < 4; ks++) {
            uint32_t bh[2][4];
            #pragma unroll
            for (int half = 0; half < 2; half++) {
                uint32_t off = SWZ((uint32_t)((b_row + half * 16) * ROWB +
                                              (b_col + ks * 16) * 2));
                ldsm4(bh[half][0], bh[half][1], bh[half][2], bh[half][3], b_b + off);
            }
            #pragma unroll
            for (int mt = 0; mt < 2; mt++) {
                uint32_t off = SWZ((uint32_t)((a_row + mt * 16) * ROWB +
                                              (a_col + ks * 16) * 2));
                uint32_t ah[4];
                ldsm4(ah[0], ah[1], ah[2], ah[3], a_b + off);
                #pragma unroll
                for (int nt = 0; nt < 4; nt++) {
                    uint32_t b0 = bh[nt >> 1][(nt & 1) * 2];
                    uint32_t b1 = bh[nt >> 1][(nt & 1) * 2 + 1];
                    mma16816(acc[mt][nt], ah, b0, b1);
                }
            }
        }
    };

    // prologue: B chunks 0,1 in flight; A chunk 0 in smem; A chunk 1 in regs
    issue_b(0, 0);
    issue_b(1, 1);
    load_a(0);
    store_a(0);
    load_a(1);

    #pragma unroll 1
    for (int c = 0; c < CHUNKS; c++) {
        if (c + 1 < CHUNKS) CP_WAIT(1);     // chunk c's B done; c+1 in flight
        else                CP_WAIT(0);
        __syncthreads();                     // orders stage reuse for all warps
        if (c + 1 < CHUNKS) store_a((c + 1) & 1);
        if (c + 2 < CHUNKS) {
            load_a(c + 2);
            issue_b(c + 2, (c + 2) % B_STAGES);
        }
        compute(c);
    }

    // ------------------ fused epilogue ------------------
    float* sc    = (float*)(smem_raw + OFF_SC);
    float* sgv   = (float*)(smem_raw + OFF_SGV);
    int*   sgi   = (int*)(smem_raw + OFF_SGI);
    int*   s_cnt = (int*)(smem_raw + OFF_CNT);
    int*   s_lst = (int*)(smem_raw + OFF_LIST);

    __syncthreads();    // compute done in all warps before smem reuse
    if (tid == 0) *s_cnt = 0;

    // acc -> smem logits
    #pragma unroll
    for (int mt = 0; mt < 2; mt++) {
        const int r0 = mt * 16 + (lid >> 2);
        #pragma unroll
        for (int nt = 0; nt < 4; nt++) {
            const int col = wid * 32 + nt * 8 + (lid & 3) * 2;
            sc[r0 * SC_PAD + col]           = acc[mt][nt][0];
            sc[r0 * SC_PAD + col + 1]       = acc[mt][nt][1];
            sc[(r0 + 8) * SC_PAD + col]     = acc[mt][nt][2];
            sc[(r0 + 8) * SC_PAD + col + 1] = acc[mt][nt][3];
        }
    }
    __syncthreads();

    // coalesced logits writeback from smem
    #pragma unroll 4
    for (int r = 0; r < BM; r++)
        C[(size_t)(bm + r) * N_EXPERTS + tid] = sc[r * SC_PAD + tid];

    // per-(token, group) top-4 scan
    if (tid < 128) {
        const int token = tid >> 2;
        const int g = tid & 3;
        const int base = g * GROUP_SIZE;
        const int ro = token * SC_PAD;
        float v0 = -1e30f, v1 = -1e30f, v2 = -1e30f, v3 = -1e30f;
        int i0 = 0, i1 = 0, i2 = 0, i3 = 0;
        #pragma unroll 8
        for (int j = 0; j < GROUP_SIZE; j++) {
            int jj = (j + 8 * g) & 63;
            float x = sc[ro + base + jj];
            int ix = base + jj;
            if (x > v0)      { v3=v2;i3=i2; v2=v1;i2=i1; v1=v0;i1=i0; v0=x;i0=ix; }
            else if (x > v1) { v3=v2;i3=i2; v2=v1;i2=i1; v1=x;i1=ix; }
            else if (x > v2) { v3=v2;i3=i2; v2=x;i2=ix; }
            else if (x > v3) { v3=x;i3=ix; }
        }
        const int o = token * 16 + g * 4;
        sgv[o] = v0; sgv[o+1] = v1; sgv[o+2] = v2; sgv[o+3] = v3;
        sgi[o] = i0; sgi[o+1] = i1; sgi[o+2] = i2; sgi[o+3] = i3;
    }
    __syncthreads();

    // flag near-tie tokens
    if (tid < 32) {
        bool f = false;
        #pragma unroll
        for (int g = 0; g < N_GROUP; g++) {
            const int o = tid * 16 + g * 4;
            float v0 = sgv[o], v1 = sgv[o+1], v2 = sgv[o+2];
            f |= ((v0 - v1) < TIE_DELTA) || ((v1 - v2) < TIE_DELTA);
        }
        if (f) { int p = atomicAdd(s_cnt, 1); s_lst[p] = tid; }
    }
    __syncthreads();

    const int cnt = *s_cnt;
    for (int it = 0; it < cnt; it++) {
        const int token = s_lst[it];
        {
            const int cand = tid >> 4;      // 0..15
            const int ln = tid & 15;
            const int e = sgi[token * 16 + cand];
            const float* hrow = A + (size_t)(bm + token) * D_MODEL;
            const float* wrow = Bw + (size_t)e * D_MODEL;
            float p = 0.0f;
            #pragma unroll 8
            for (int k = 0; k < D_MODEL / 16; k++)
                p = fmaf(hrow[ln + 16 * k], wrow[ln + 16 * k], p);
            #pragma unroll
            for (int off = 8; off; off >>= 1)
                p += __shfl_down_sync(0xffffffffu, p, off, 16);
            if (ln == 0) sgv[token * 16 + cand] = p;
        }
        __syncthreads();
        if (tid < 4) {
            const int o = token * 16 + tid * 4;
            #pragma unroll
            for (int a = 0; a < 3; a++) {
                int best = a;
                #pragma unroll
                for (int b = 1; b < 4; b++) {
                    if (b <= a) continue;
                    if (sgv[o+b] > sgv[o+best] ||
                        (sgv[o+b] == sgv[o+best] && sgi[o+b] < sgi[o+best]))
                        best = b;
                }
                float tv = sgv[o+a]; sgv[o+a] = sgv[o+best]; sgv[o+best] = tv;
                int ti = sgi[o+a]; sgi[o+a] = sgi[o+best]; sgi[o+best] = ti;
            }
        }
        __syncthreads();
    }

    // final outputs
    if (tid < 32) {
        float w8[8]; int i8[8];
        float sum = 0.0f;
        #pragma unroll
        for (int g = 0; g < N_GROUP; g++) {
            #pragma unroll
            for (int k = 0; k < 2; k++) {
                const int o = tid * 16 + g * 4 + k;
                float s = 1.0f / (1.0f + __expf(-sgv[o]));
                w8[g * 2 + k] = s;
                i8[g * 2 + k] = sgi[o];
                sum += s;
            }
        }
        float scale = ROUTED_SCALING / (sum + EPS_ROUTE);
        #pragma unroll
        for (int j = 0; j < 8; j++) {
            out_idx[(size_t)(bm + tid) * 8 + j] = (float)i8[j];
            out_w[(size_t)(bm + tid) * 8 + j]   = w8[j] * scale;
        }
    }
}

// ---------------------------------------------------------------------------
// Launch
// ---------------------------------------------------------------------------
extern "C" void kernel_launch(void* const* d_in, const int* in_sizes, int n_in,
                              void* d_out, int out_size) {
    const float* hidden = (const float*)d_in[0];   // [8192, 4096]
    const float* gate_w = (const float*)d_in[1];   // [256, 4096]

    float* out = (float*)d_out;
    float* out_idx    = out;
    float* out_w      = out + (size_t)N_TOKENS * 8;
    float* out_logits = out + (size_t)N_TOKENS * 16;

    convert_b<<<256, 256>>>(gate_w);

    cudaFuncSetAttribute(gemm_gate_fused,
                         cudaFuncAttributeMaxDynamicSharedMemorySize, GEMM_SMEM);
    gemm_gate_fused<<<N_TOKENS / BM, 256, GEMM_SMEM>>>(
        hidden, gate_w, out_logits, out_idx, out_w);
}

// round 13
// speedup vs baseline: 1.2470x; 1.0296x over previous
#include <cuda_runtime.h>
#include <cuda_fp16.h>
#include <cstdint>

#define N_TOKENS   8192
#define N_EXPERTS  256
#define D_MODEL    4096
#define N_GROUP    4
#define GROUP_SIZE 64
#define ROUTED_SCALING 2.5f
#define EPS_ROUTE  1e-10f
#define TIE_DELTA  1.2e-3f

// GEMM tiling: block 32x256, BK=64, 256 threads (8 warps, warp tile 32x32)
#define BM 32
#define BN 256
#define BK 64
#define CHUNKS (D_MODEL / BK)        // 64

// SMEM geometry: exact 128-B rows (64 fp16), SW128 XOR swizzle, no padding.
#define ROWB        128                      // bytes per row
#define A_BYTES     (32 * ROWB)              // 4096
#define B_BYTES     (256 * ROWB)             // 32768
#define A_STAGES    2
#define B_STAGES    3
#define OFF_B       (A_STAGES * A_BYTES)     // 8192
#define GEMM_SMEM   (OFF_B + B_STAGES * B_BYTES)   // 106496 (104 KB)

// SW128 swizzle on byte offsets (XOR bits [4:6] with row bits [7:9])
#define SWZ(x) ((x) ^ (((x) >> 3) & 0x70))

// Epilogue smem views (reuse tile memory; all < GEMM_SMEM)
#define SC_PAD   257
#define OFF_SC   0                        // 32*257 floats = 32896 B
#define OFF_SGV  32896                    // 32*16 floats  = 2048 B
#define OFF_SGI  (32896 + 2048)           // 32*16 ints    = 2048 B
#define OFF_CNT  (32896 + 4096)           // 1 int
#define OFF_LIST (32896 + 4096 + 16)      // 32 ints

// ---------------------------------------------------------------------------
// Scratch: fp16 copy of gate_w
// ---------------------------------------------------------------------------
__device__ __half g_Bh[(size_t)N_EXPERTS * D_MODEL];

// ---------------------------------------------------------------------------
// helpers
// ---------------------------------------------------------------------------
__device__ __forceinline__ uint32_t smem_u32(const void* p) {
    uint32_t a;
    asm("{ .reg .u64 t; cvta.to.shared.u64 t, %1; cvt.u32.u64 %0, t; }"
        : "=r"(a) : "l"(p));
    return a;
}

__device__ __forceinline__ void ldsm4(uint32_t& r0, uint32_t& r1,
                                      uint32_t& r2, uint32_t& r3, uint32_t addr) {
    asm volatile("ldmatrix.sync.aligned.m8n8.x4.shared.b16 {%0,%1,%2,%3}, [%4];"
                 : "=r"(r0), "=r"(r1), "=r"(r2), "=r"(r3) : "r"(addr));
}

__device__ __forceinline__ void mma16816(float* c, const uint32_t* a,
                                         uint32_t b0, uint32_t b1) {
    asm volatile(
        "mma.sync.aligned.m16n8k16.row.col.f32.f16.f16.f32 "
        "{%0,%1,%2,%3}, {%4,%5,%6,%7}, {%8,%9}, {%0,%1,%2,%3};"
        : "+f"(c[0]), "+f"(c[1]), "+f"(c[2]), "+f"(c[3])
        : "r"(a[0]), "r"(a[1]), "r"(a[2]), "r"(a[3]), "r"(b0), "r"(b1));
}

__device__ __forceinline__ uint32_t pack_h2(float a, float b) {
    __half2 h = __floats2half2_rn(a, b);
    return *(uint32_t*)&h;
}

#define CP16(dst, src) \
    asm volatile("cp.async.cg.shared.global [%0], [%1], 16;" :: "r"(dst), "l"(src) : "memory")
#define CP_COMMIT() asm volatile("cp.async.commit_group;" ::: "memory")
#define CP_WAIT(n)  asm volatile("cp.async.wait_group %0;" :: "n"(n) : "memory")

// ---------------------------------------------------------------------------
// B convert: fp32 -> fp16
// ---------------------------------------------------------------------------
__global__ __launch_bounds__(256) void convert_b(const float* __restrict__ src) {
    int i = blockIdx.x * blockDim.x + threadIdx.x;
    const int n4 = N_EXPERTS * D_MODEL / 4;
    const int stride = gridDim.x * blockDim.x;
    const float4* s4 = (const float4*)src;
    uint2* h2 = (uint2*)g_Bh;
    for (; i < n4; i += stride) {
        float4 v = s4[i];
        h2[i] = make_uint2(pack_h2(v.x, v.y), pack_h2(v.z, v.w));
    }
}

// ---------------------------------------------------------------------------
// Fused fp16 GEMM + MoE gate epilogue. 256 threads, 2 CTAs/SM.
// 3-stage B ring; producer work issued BEFORE the wait; wait targets only
// the chunk actually consumed (effective lookahead ~2).
// ---------------------------------------------------------------------------
__global__ __launch_bounds__(256, 2) void gemm_gate_fused(
    const float* __restrict__ A,     // [8192, 4096] hidden
    const float* __restrict__ Bw,    // [256, 4096] gate_w fp32 (exact redo)
    float* __restrict__ C,           // [8192, 256] logits out
    float* __restrict__ out_idx,     // [8192, 8]
    float* __restrict__ out_w)       // [8192, 8]
{
    extern __shared__ __align__(128) char smem_raw[];
    const uint32_t sb = smem_u32(smem_raw);

    const int tid = threadIdx.x;
    const int lid = tid & 31;
    const int wid = tid >> 5;            // 0..7 -> n slice [wid*32, +32)
    const int bm = blockIdx.x * BM;

    // A global-load mapping: 8 threads/row, 8 floats each (32x64 fp32 tile)
    const int ar = tid >> 3;             // 0..31
    const int ac = (tid & 7) * 8;        // col (elements)

    float4 buf[2];                       // A prefetch registers
    float acc[2][4][4];
    #pragma unroll
    for (int i = 0; i < 2; i++)
        #pragma unroll
        for (int j = 0; j < 4; j++)
            #pragma unroll
            for (int k = 0; k < 4; k++) acc[i][j][k] = 0.0f;

    // ldmatrix coords (rows; cols in elements)
    const int a_row = lid & 15;
    const int a_col = (lid >> 4) * 8;
    const int b_row = wid * 32 + ((lid >> 4) << 3) + (lid & 7);
    const int b_col = ((lid >> 3) & 1) * 8;

    const __half* gB = g_Bh;

    auto issue_b = [&](int c, int s) {
        const int k0 = c * BK;
        const uint32_t b_s = sb + OFF_B + s * B_BYTES;
        #pragma unroll
        for (int i = 0; i < 8; i++) {
            int id = i * 256 + tid;       // 0..2047
            int row = id >> 3, sg = id & 7;
            uint32_t doff = SWZ((uint32_t)(row * ROWB + sg * 16));
            CP16(b_s + doff, gB + (size_t)row * D_MODEL + k0 + sg * 8);
        }
        CP_COMMIT();
    };

    auto load_a = [&](int c) {
        const int k0 = c * BK;
        const float* base = A + (size_t)(bm + ar) * D_MODEL + k0 + ac;
        buf[0] = *(const float4*)(base);
        buf[1] = *(const float4*)(base + 4);
    };

    auto store_a = [&](int s) {
        uint32_t hw[4];
        hw[0] = pack_h2(buf[0].x, buf[0].y);
        hw[1] = pack_h2(buf[0].z, buf[0].w);
        hw[2] = pack_h2(buf[1].x, buf[1].y);
        hw[3] = pack_h2(buf[1].z, buf[1].w);
        uint32_t doff = SWZ((uint32_t)(ar * ROWB + ac * 2));
        *(uint4*)(smem_raw + s * A_BYTES + doff) = make_uint4(hw[0], hw[1], hw[2], hw[3]);
    };

    auto compute = [&](int s) {
        const uint32_t a_b = sb + (s & 1) * A_BYTES;
        const uint32_t b_b = sb + OFF_B + (s % B_STAGES) * B_BYTES;
        #pragma unroll
        for (int ks = 0; ks < 4; ks++) {
            uint32_t bh[2][4];
            #pragma unroll
            for (int half = 0; half < 2; half++) {
                uint32_t off = SWZ((uint32_t)((b_row + half * 16) * ROWB +
                                              (b_col + ks * 16) * 2));
                ldsm4(bh[half][0], bh[half][1], bh[half][2], bh[half][3], b_b + off);
            }
            #pragma unroll
            for (int mt = 0; mt < 2; mt++) {
                uint32_t off = SWZ((uint32_t)((a_row + mt * 16) * ROWB +
                                              (a_col + ks * 16) * 2));
                uint32_t ah[4];
                ldsm4(ah[0], ah[1], ah[2], ah[3], a_b + off);
                #pragma unroll
                for (int nt = 0; nt < 4; nt++) {
                    uint32_t b0 = bh[nt >> 1][(nt & 1) * 2];
                    uint32_t b1 = bh[nt >> 1][(nt & 1) * 2 + 1];
                    mma16816(acc[mt][nt], ah, b0, b1);
                }
            }
        }
    };

    // prologue: B chunks 0,1 in flight; A chunk 0 in smem; A chunk 1 in regs
    issue_b(0, 0);
    issue_b(1, 1);
    load_a(0);
    store_a(0);
    load_a(1);

    #pragma unroll 1
    for (int c = 0; c < CHUNKS; c++) {
        __syncthreads();                 // prior compute done -> stages reusable
        if (c + 1 < CHUNKS) store_a((c + 1) & 1);
        if (c + 2 < CHUNKS) {
            load_a(c + 2);
            issue_b(c + 2, (c + 2) % B_STAGES);
            CP_WAIT(2);                  // exactly chunk c's B complete
        } else if (c + 1 < CHUNKS) {
            CP_WAIT(1);                  // c=CHUNKS-2: c done, c+1 in flight
        } else {
            CP_WAIT(0);                  // last chunk: drain
        }
        compute(c);
    }

    // ------------------ fused epilogue ------------------
    float* sc    = (float*)(smem_raw + OFF_SC);
    float* sgv   = (float*)(smem_raw + OFF_SGV);
    int*   sgi   = (int*)(smem_raw + OFF_SGI);
    int*   s_cnt = (int*)(smem_raw + OFF_CNT);
    int*   s_lst = (int*)(smem_raw + OFF_LIST);

    __syncthreads();    // compute done in all warps before smem reuse
    if (tid == 0) *s_cnt = 0;

    // acc -> smem logits
    #pragma unroll
    for (int mt = 0; mt < 2; mt++) {
        const int r0 = mt * 16 + (lid >> 2);
        #pragma unroll
        for (int nt = 0; nt < 4; nt++) {
            const int col = wid * 32 + nt * 8 + (lid & 3) * 2;
            sc[r0 * SC_PAD + col]           = acc[mt][nt][0];
            sc[r0 * SC_PAD + col + 1]       = acc[mt][nt][1];
            sc[(r0 + 8) * SC_PAD + col]     = acc[mt][nt][2];
            sc[(r0 + 8) * SC_PAD + col + 1] = acc[mt][nt][3];
        }
    }
    __syncthreads();

    // coalesced logits writeback from smem
    #pragma unroll 4
    for (int r = 0; r < BM; r++)
        C[(size_t)(bm + r) * N_EXPERTS + tid] = sc[r * SC_PAD + tid];

    // per-(token, group) top-4 scan
    if (tid < 128) {
        const int token = tid >> 2;
        const int g = tid & 3;
        const int base = g * GROUP_SIZE;
        const int ro = token * SC_PAD;
        float v0 = -1e30f, v1 = -1e30f, v2 = -1e30f, v3 = -1e30f;
        int i0 = 0, i1 = 0, i2 = 0, i3 = 0;
        #pragma unroll 8
        for (int j = 0; j < GROUP_SIZE; j++) {
            int jj = (j + 8 * g) & 63;
            float x = sc[ro + base + jj];
            int ix = base + jj;
            if (x > v0)      { v3=v2;i3=i2; v2=v1;i2=i1; v1=v0;i1=i0; v0=x;i0=ix; }
            else if (x > v1) { v3=v2;i3=i2; v2=v1;i2=i1; v1=x;i1=ix; }
            else if (x > v2) { v3=v2;i3=i2; v2=x;i2=ix; }
            else if (x > v3) { v3=x;i3=ix; }
        }
        const int o = token * 16 + g * 4;
        sgv[o] = v0; sgv[o+1] = v1; sgv[o+2] = v2; sgv[o+3] = v3;
        sgi[o] = i0; sgi[o+1] = i1; sgi[o+2] = i2; sgi[o+3] = i3;
    }
    __syncthreads();

    // flag near-tie tokens
    if (tid < 32) {
        bool f = false;
        #pragma unroll
        for (int g = 0; g < N_GROUP; g++) {
            const int o = tid * 16 + g * 4;
            float v0 = sgv[o], v1 = sgv[o+1], v2 = sgv[o+2];
            f |= ((v0 - v1) < TIE_DELTA) || ((v1 - v2) < TIE_DELTA);
        }
        if (f) { int p = atomicAdd(s_cnt, 1); s_lst[p] = tid; }
    }
    __syncthreads();

    const int cnt = *s_cnt;
    for (int it = 0; it < cnt; it++) {
        const int token = s_lst[it];
        {
            const int cand = tid >> 4;      // 0..15
            const int ln = tid & 15;
            const int e = sgi[token * 16 + cand];
            const float* hrow = A + (size_t)(bm + token) * D_MODEL;
            const float* wrow = Bw + (size_t)e * D_MODEL;
            float p = 0.0f;
            #pragma unroll 8
            for (int k = 0; k < D_MODEL / 16; k++)
                p = fmaf(hrow[ln + 16 * k], wrow[ln + 16 * k], p);
            #pragma unroll
            for (int off = 8; off; off >>= 1)
                p += __shfl_down_sync(0xffffffffu, p, off, 16);
            if (ln == 0) sgv[token * 16 + cand] = p;
        }
        __syncthreads();
        if (tid < 4) {
            const int o = token * 16 + tid * 4;
            #pragma unroll
            for (int a = 0; a < 3; a++) {
                int best = a;
                #pragma unroll
                for (int b = 1; b < 4; b++) {
                    if (b <= a) continue;
                    if (sgv[o+b] > sgv[o+best] ||
                        (sgv[o+b] == sgv[o+best] && sgi[o+b] < sgi[o+best]))
                        best = b;
                }
                float tv = sgv[o+a]; sgv[o+a] = sgv[o+best]; sgv[o+best] = tv;
                int ti = sgi[o+a]; sgi[o+a] = sgi[o+best]; sgi[o+best] = ti;
            }
        }
        __syncthreads();
    }

    // final outputs
    if (tid < 32) {
        float w8[8]; int i8[8];
        float sum = 0.0f;
        #pragma unroll
        for (int g = 0; g < N_GROUP; g++) {
            #pragma unroll
            for (int k = 0; k < 2; k++) {
                const int o = tid * 16 + g * 4 + k;
                float s = 1.0f / (1.0f + __expf(-sgv[o]));
                w8[g * 2 + k] = s;
                i8[g * 2 + k] = sgi[o];
                sum += s;
            }
        }
        float scale = ROUTED_SCALING / (sum + EPS_ROUTE);
        #pragma unroll
        for (int j = 0; j < 8; j++) {
            out_idx[(size_t)(bm + tid) * 8 + j] = (float)i8[j];
            out_w[(size_t)(bm + tid) * 8 + j]   = w8[j] * scale;
        }
    }
}

// ---------------------------------------------------------------------------
// Launch
// ---------------------------------------------------------------------------
extern "C" void kernel_launch(void* const* d_in, const int* in_sizes, int n_in,
                              void* d_out, int out_size) {
    const float* hidden = (const float*)d_in[0];   // [8192, 4096]
    const float* gate_w = (const float*)d_in[1];   // [256, 4096]

    float* out = (float*)d_out;
    float* out_idx    = out;
    float* out_w      = out + (size_t)N_TOKENS * 8;
    float* out_logits = out + (size_t)N_TOKENS * 16;

    convert_b<<<256, 256>>>(gate_w);

    cudaFuncSetAttribute(gemm_gate_fused,
                         cudaFuncAttributeMaxDynamicSharedMemorySize, GEMM_SMEM);
    gemm_gate_fused<<<N_TOKENS / BM, 256, GEMM_SMEM>>>(
        hidden, gate_w, out_logits, out_idx, out_w);
}